// round 1
// baseline (speedup 1.0000x reference)
#include <cuda_runtime.h>
#include <cstdint>

#define NN   50000
#define EE   800000
#define PP   3
#define HH   4
#define DD   64
#define CIN  256          // H*D = in_size
#define EPS  1e-5f
#define SLOPE 0.2f

// ---------------- device scratch (static, no allocation) ----------------
__device__ __align__(256) float    g_feat [(size_t)PP*NN*CIN];   // projected features per path
__device__ __align__(256) float    g_accum[(size_t)PP*NN*CIN];   // GAT output accumulator, then x = relu(out)+h
__device__ __align__(256) float    g_escore[(size_t)PP*EE*HH];   // edge scores, then exp values
__device__ __align__(16)  float    g_el   [PP*NN*HH];
__device__ __align__(16)  float    g_er   [PP*NN*HH];
__device__ __align__(16)  unsigned g_m    [PP*NN*HH];            // segment max (order-preserving uint keys)
__device__ __align__(16)  float    g_denom[PP*NN*HH];
__device__ float g_sum  [PP*CIN];
__device__ float g_sumsq[PP*CIN];
__device__ float g_scale[PP*CIN];
__device__ float g_shift[PP*CIN];

// order-preserving float->uint key (monotone under unsigned compare)
__device__ __forceinline__ unsigned fkey(float f) {
    unsigned u = __float_as_uint(f);
    return (u & 0x80000000u) ? ~u : (u | 0x80000000u);
}
__device__ __forceinline__ float kinv(unsigned k) {
    unsigned u = (k & 0x80000000u) ? (k ^ 0x80000000u) : ~k;
    return __uint_as_float(u);
}

__device__ __forceinline__ void red_add_v4(float* p, float4 v) {
    asm volatile("red.global.add.v4.f32 [%0], {%1,%2,%3,%4};"
                 :: "l"(p), "f"(v.x), "f"(v.y), "f"(v.z), "f"(v.w) : "memory");
}

// ---------------- K0: zero scratch ----------------
__global__ void k_zero() {
    size_t i = (size_t)blockIdx.x * blockDim.x + threadIdx.x;
    size_t n4 = (size_t)PP * NN * CIN / 4;
    if (i < n4) ((float4*)g_accum)[i] = make_float4(0.f, 0.f, 0.f, 0.f);
    if (i < (size_t)PP * NN * HH / 4) {
        ((uint4*)g_m)[i]      = make_uint4(0u, 0u, 0u, 0u);
        ((float4*)g_denom)[i] = make_float4(0.f, 0.f, 0.f, 0.f);
    }
    if (i < (size_t)PP * CIN) { g_sum[i] = 0.f; g_sumsq[i] = 0.f; }
}

// ---------------- Kw: semantic weights w = mask / rowsum ----------------
__global__ void k_w(const float* __restrict__ mask, float* __restrict__ wout) {
    int n = blockIdx.x * blockDim.x + threadIdx.x;
    if (n >= NN) return;
    float m0 = mask[n*PP+0], m1 = mask[n*PP+1], m2 = mask[n*PP+2];
    float inv = 1.f / (m0 + m1 + m2);
    wout[n*PP+0] = m0 * inv;
    wout[n*PP+1] = m1 * inv;
    wout[n*PP+2] = m2 * inv;
}

// ---------------- K1: feat[p] = h @ fc_w[p]  (fp32 tiled GEMM) ----------------
#define BM 64
#define BN 64
#define BK 16
__global__ void k_gemm(const float* __restrict__ A, const float* __restrict__ W) {
    int p = blockIdx.z;
    const float* B = W + (size_t)p * CIN * CIN;
    float* C = g_feat + (size_t)p * NN * CIN;

    __shared__ float As[BK][BM + 4];   // +4 keeps 16B row alignment (272B rows)
    __shared__ float Bs[BK][BN];

    int tid = threadIdx.x;             // 256 threads
    int m0 = blockIdx.y * BM, n0 = blockIdx.x * BN;
    int tx = tid & 15, ty = tid >> 4;

    int ar = tid >> 2;                 // A-tile row 0..63
    int ac = (tid & 3) * 4;            // A-tile k-col {0,4,8,12}
    int br = tid >> 4;                 // B-tile k-row 0..15
    int bc = (tid & 15) * 4;           // B-tile col

    float acc[4][4] = {};

    for (int k0 = 0; k0 < CIN; k0 += BK) {
        int grow = m0 + ar;
        float4 a4 = (grow < NN) ? *(const float4*)(A + (size_t)grow * CIN + k0 + ac)
                                : make_float4(0.f, 0.f, 0.f, 0.f);
        As[ac+0][ar] = a4.x; As[ac+1][ar] = a4.y; As[ac+2][ar] = a4.z; As[ac+3][ar] = a4.w;
        *(float4*)&Bs[br][bc] = *(const float4*)(B + (size_t)(k0 + br) * CIN + n0 + bc);
        __syncthreads();

        #pragma unroll
        for (int k = 0; k < BK; k++) {
            float4 av = *(const float4*)&As[k][ty * 4];
            float4 bv = *(const float4*)&Bs[k][tx * 4];
            float a[4] = {av.x, av.y, av.z, av.w};
            float b[4] = {bv.x, bv.y, bv.z, bv.w};
            #pragma unroll
            for (int i = 0; i < 4; i++)
                #pragma unroll
                for (int j = 0; j < 4; j++)
                    acc[i][j] += a[i] * b[j];
        }
        __syncthreads();
    }

    #pragma unroll
    for (int i = 0; i < 4; i++) {
        int r = m0 + ty * 4 + i;
        if (r < NN)
            *(float4*)(C + (size_t)r * CIN + n0 + tx * 4) =
                make_float4(acc[i][0], acc[i][1], acc[i][2], acc[i][3]);
    }
}

// ---------------- K2: el/er per (node, head) ----------------
__global__ void k_elr(const float* __restrict__ al, const float* __restrict__ ar_) {
    int idx = blockIdx.x * blockDim.x + threadIdx.x;
    int p = blockIdx.z;
    if (idx >= NN * HH) return;
    int n = idx >> 2, hh = idx & 3;
    const float* f = g_feat + ((size_t)p * NN + n) * CIN + hh * DD;
    const float* a = al  + (size_t)(p * HH + hh) * DD;
    const float* b = ar_ + (size_t)(p * HH + hh) * DD;
    float sl = 0.f, sr = 0.f;
    #pragma unroll
    for (int d = 0; d < DD; d += 4) {
        float4 f4 = *(const float4*)(f + d);
        float4 a4 = *(const float4*)(a + d);
        float4 b4 = *(const float4*)(b + d);
        sl += f4.x*a4.x + f4.y*a4.y + f4.z*a4.z + f4.w*a4.w;
        sr += f4.x*b4.x + f4.y*b4.y + f4.z*b4.z + f4.w*b4.w;
    }
    g_el[(p * NN + n) * HH + hh] = sl;
    g_er[(p * NN + n) * HH + hh] = sr;
}

// ---------------- K3: edge scores + segment max ----------------
__global__ void k_edge1(const int* __restrict__ src, const int* __restrict__ dst) {
    int e = blockIdx.x * blockDim.x + threadIdx.x;
    int p = blockIdx.z;
    if (e >= EE) return;
    int s = src[p * EE + e], d = dst[p * EE + e];
    float4 a = *(const float4*)(g_el + (p * NN + s) * HH);
    float4 b = *(const float4*)(g_er + (p * NN + d) * HH);
    float v[4] = {a.x + b.x, a.y + b.y, a.z + b.z, a.w + b.w};
    #pragma unroll
    for (int i = 0; i < 4; i++) v[i] = v[i] > 0.f ? v[i] : SLOPE * v[i];
    *(float4*)(g_escore + ((size_t)p * EE + e) * HH) = make_float4(v[0], v[1], v[2], v[3]);
    unsigned* mp = g_m + (p * NN + d) * HH;
    #pragma unroll
    for (int i = 0; i < 4; i++) atomicMax(mp + i, fkey(v[i]));
}

// ---------------- K4: exp(e - m) + segment sum ----------------
__global__ void k_edge2(const int* __restrict__ dst) {
    int e = blockIdx.x * blockDim.x + threadIdx.x;
    int p = blockIdx.z;
    if (e >= EE) return;
    int d = dst[p * EE + e];
    float* sp = g_escore + ((size_t)p * EE + e) * HH;
    float4 sc = *(const float4*)sp;
    const unsigned* mp = g_m + (p * NN + d) * HH;
    float4 ex;
    ex.x = expf(sc.x - kinv(mp[0]));
    ex.y = expf(sc.y - kinv(mp[1]));
    ex.z = expf(sc.z - kinv(mp[2]));
    ex.w = expf(sc.w - kinv(mp[3]));
    *(float4*)sp = ex;
    red_add_v4(g_denom + (p * NN + d) * HH, ex);
}

// ---------------- K5: alpha·feat[src] -> accum[dst] scatter, attn mean ----------------
__global__ void k_scatter(const int* __restrict__ src, const int* __restrict__ dst,
                          float* __restrict__ attn_out) {
    int p = blockIdx.z;
    int gwarp = (blockIdx.x * blockDim.x + threadIdx.x) >> 5;
    int lane = threadIdx.x & 31;
    if (gwarp >= EE) return;
    int e = gwarp;
    int s = src[p * EE + e], d = dst[p * EE + e];
    float4 ex = *(const float4*)(g_escore + ((size_t)p * EE + e) * HH);
    float4 dn = *(const float4*)(g_denom + (p * NN + d) * HH);
    float al4[4] = {ex.x / dn.x, ex.y / dn.y, ex.z / dn.z, ex.w / dn.w};
    if (lane == 0)
        attn_out[(size_t)p * EE + e] = 0.25f * (al4[0] + al4[1] + al4[2] + al4[3]);
    const float* fs = g_feat  + ((size_t)p * NN + s) * CIN;
    float*       od = g_accum + ((size_t)p * NN + d) * CIN;
    #pragma unroll
    for (int k = 0; k < 2; k++) {
        int c = lane + 32 * k;            // float4 chunk id 0..63
        float a = al4[c >> 4];            // head = (c*4)/64
        float4 f4 = *(const float4*)(fs + c * 4);
        red_add_v4(od + c * 4, make_float4(f4.x * a, f4.y * a, f4.z * a, f4.w * a));
    }
}

// ---------------- K6: x = relu(out) + h ; accumulate BN stats ----------------
#define ROWS_PER_BLOCK 100
__global__ void k_stats(const float* __restrict__ h) {
    int p = blockIdx.z;
    int c = threadIdx.x;                  // 256 channels
    int r0 = blockIdx.x * ROWS_PER_BLOCK;
    float s = 0.f, q = 0.f;
    for (int r = r0; r < r0 + ROWS_PER_BLOCK; r++) {
        size_t i = ((size_t)p * NN + r) * CIN + c;
        float x = fmaxf(g_accum[i], 0.f) + h[(size_t)r * CIN + c];
        g_accum[i] = x;
        s += x; q += x * x;
    }
    atomicAdd(&g_sum[p * CIN + c], s);
    atomicAdd(&g_sumsq[p * CIN + c], q);
}

// ---------------- K7: finalize BN affine per channel ----------------
__global__ void k_bnfin(const float* __restrict__ gamma, const float* __restrict__ beta) {
    int p = blockIdx.z; int c = threadIdx.x;
    float mu  = g_sum[p * CIN + c] * (1.f / NN);
    float var = g_sumsq[p * CIN + c] * (1.f / NN) - mu * mu;
    float sc = gamma[c] * rsqrtf(var + EPS);
    g_scale[p * CIN + c] = sc;
    g_shift[p * CIN + c] = beta[c] - sc * mu;
}

// ---------------- K8: pooled = sum_p w[n,p] * (scale*x + shift) ----------------
__global__ void k_pool(const float* __restrict__ wmat, float* __restrict__ pooled) {
    int idx = blockIdx.x * blockDim.x + threadIdx.x;   // over N * 64 float4-chunks
    if (idx >= NN * 64) return;
    int n = idx >> 6, c4 = (idx & 63) * 4;
    float4 acc = make_float4(0.f, 0.f, 0.f, 0.f);
    #pragma unroll
    for (int p = 0; p < PP; p++) {
        float wv = wmat[n * PP + p];
        float4 x  = *(const float4*)(g_accum + ((size_t)p * NN + n) * CIN + c4);
        float4 sc = *(const float4*)(g_scale + p * CIN + c4);
        float4 sh = *(const float4*)(g_shift + p * CIN + c4);
        acc.x += wv * (sc.x * x.x + sh.x);
        acc.y += wv * (sc.y * x.y + sh.y);
        acc.z += wv * (sc.z * x.z + sh.z);
        acc.w += wv * (sc.w * x.w + sh.w);
    }
    *(float4*)(pooled + (size_t)n * CIN + c4) = acc;
}

// ---------------- host ----------------
extern "C" void kernel_launch(void* const* d_in, const int* in_sizes, int n_in,
                              void* d_out, int out_size) {
    const float* h     = (const float*)d_in[0];
    const float* mask  = (const float*)d_in[1];
    const int*   src   = (const int*)  d_in[2];
    const int*   dst   = (const int*)  d_in[3];
    const float* fc    = (const float*)d_in[4];
    const float* al    = (const float*)d_in[5];
    const float* ar    = (const float*)d_in[6];
    const float* gamma = (const float*)d_in[7];
    const float* beta  = (const float*)d_in[8];

    float* out    = (float*)d_out;
    float* pooled = out;                              // [N, 256]
    float* wout   = out + (size_t)NN * CIN;           // [N, 3]
    float* attn   = wout + (size_t)NN * PP;           // [3, E]

    // zero scratch (covers accum / m / denom / sums)
    {
        size_t n4 = (size_t)PP * NN * CIN / 4;
        int blocks = (int)((n4 + 255) / 256);
        k_zero<<<blocks, 256>>>();
    }

    k_w<<<(NN + 255) / 256, 256>>>(mask, wout);

    dim3 gg(CIN / BN, (NN + BM - 1) / BM, PP);
    k_gemm<<<gg, 256>>>(h, fc);

    k_elr<<<dim3((NN * HH + 255) / 256, 1, PP), 256>>>(al, ar);
    k_edge1<<<dim3((EE + 255) / 256, 1, PP), 256>>>(src, dst);
    k_edge2<<<dim3((EE + 255) / 256, 1, PP), 256>>>(dst);
    k_scatter<<<dim3(EE / 8, 1, PP), 256>>>(src, dst, attn);
    k_stats<<<dim3(NN / ROWS_PER_BLOCK, 1, PP), 256>>>(h);
    k_bnfin<<<dim3(1, 1, PP), 256>>>(gamma, beta);
    k_pool<<<(NN * 64 + 255) / 256, 256>>>(wout, pooled);
}

// round 2
// speedup vs baseline: 1.4902x; 1.4902x over previous
#include <cuda_runtime.h>
#include <cstdint>

#define NN   50000
#define EE   800000
#define PP   3
#define HH   4
#define DD   64
#define CIN  256          // H*D = in_size
#define EPS  1e-5f
#define SLOPE 0.2f

// ---------------- device scratch (static, no allocation) ----------------
__device__ __align__(256) float g_feat [(size_t)PP*NN*CIN];   // projected features per path
__device__ __align__(256) float g_accum[(size_t)PP*NN*CIN];   // x = relu(out)+h per path
__device__ __align__(16)  float g_el   [PP*NN*HH];
__device__ __align__(16)  float g_er   [PP*NN*HH];
__device__ int g_deg   [PP*NN];
__device__ int g_rowptr[PP*(NN+1)];
__device__ int g_cur   [PP*NN];
__device__ int g_eidx  [(size_t)PP*EE];
__device__ float g_sum  [PP*CIN];
__device__ float g_sumsq[PP*CIN];
__device__ float g_scale[PP*CIN];
__device__ float g_shift[PP*CIN];

// ---------------- K0: zero small scratch ----------------
__global__ void k_zero() {
    int i = blockIdx.x * blockDim.x + threadIdx.x;
    if (i < PP * NN) g_deg[i] = 0;
    if (i < PP * CIN) { g_sum[i] = 0.f; g_sumsq[i] = 0.f; }
}

// ---------------- Kw: semantic weights ----------------
__global__ void k_w(const float* __restrict__ mask, float* __restrict__ wout) {
    int n = blockIdx.x * blockDim.x + threadIdx.x;
    if (n >= NN) return;
    float m0 = mask[n*PP+0], m1 = mask[n*PP+1], m2 = mask[n*PP+2];
    float inv = 1.f / (m0 + m1 + m2);
    wout[n*PP+0] = m0 * inv;
    wout[n*PP+1] = m1 * inv;
    wout[n*PP+2] = m2 * inv;
}

// ---------------- K1: feat = h @ W, fused el/er epilogue ----------------
// 128x128 block tile, 8x8 microtile, BK=8. Thread (tx,ty): rows ty*8..+8,
// cols {tx*4..+4} (group A, head hA) and {64+tx*4..+4} (group B, head hB).
#define GM 128
#define GN 128
#define GK 8
__global__ void __launch_bounds__(256) k_gemm(
    const float* __restrict__ A, const float* __restrict__ W,
    const float* __restrict__ al, const float* __restrict__ ar_) {
    int p = blockIdx.z;
    const float* B = W + (size_t)p * CIN * CIN;
    float* C = g_feat + (size_t)p * NN * CIN;

    __shared__ float As[GK][GM + 4];   // +4 stride: conflict-free transposed stores
    __shared__ float Bs[GK][GN];

    int tid = threadIdx.x;
    int m0 = blockIdx.y * GM, n0 = blockIdx.x * GN;
    int tx = tid & 15, ty = tid >> 4;

    int arow = tid >> 1;            // 0..127
    int acol = (tid & 1) * 4;       // 0 / 4
    int brow = tid >> 5;            // 0..7
    int bcol = (tid & 31) * 4;

    float acc[8][8];
    #pragma unroll
    for (int i = 0; i < 8; i++)
        #pragma unroll
        for (int j = 0; j < 8; j++) acc[i][j] = 0.f;

    for (int k0 = 0; k0 < CIN; k0 += GK) {
        int gr = m0 + arow;
        float4 a4 = (gr < NN) ? *(const float4*)(A + (size_t)gr * CIN + k0 + acol)
                              : make_float4(0.f, 0.f, 0.f, 0.f);
        As[acol+0][arow] = a4.x; As[acol+1][arow] = a4.y;
        As[acol+2][arow] = a4.z; As[acol+3][arow] = a4.w;
        *(float4*)&Bs[brow][bcol] = *(const float4*)(B + (size_t)(k0 + brow) * CIN + n0 + bcol);
        __syncthreads();

        #pragma unroll
        for (int kk = 0; kk < GK; kk++) {
            float4 ra0 = *(const float4*)&As[kk][ty * 8];
            float4 ra1 = *(const float4*)&As[kk][ty * 8 + 4];
            float4 rb0 = *(const float4*)&Bs[kk][tx * 4];
            float4 rb1 = *(const float4*)&Bs[kk][64 + tx * 4];
            float ra[8] = {ra0.x, ra0.y, ra0.z, ra0.w, ra1.x, ra1.y, ra1.z, ra1.w};
            float rb[8] = {rb0.x, rb0.y, rb0.z, rb0.w, rb1.x, rb1.y, rb1.z, rb1.w};
            #pragma unroll
            for (int i = 0; i < 8; i++)
                #pragma unroll
                for (int j = 0; j < 8; j++)
                    acc[i][j] += ra[i] * rb[j];
        }
        __syncthreads();
    }

    // store C
    #pragma unroll
    for (int i = 0; i < 8; i++) {
        int r = m0 + ty * 8 + i;
        if (r < NN) {
            *(float4*)(C + (size_t)r * CIN + n0 + tx * 4) =
                make_float4(acc[i][0], acc[i][1], acc[i][2], acc[i][3]);
            *(float4*)(C + (size_t)r * CIN + n0 + 64 + tx * 4) =
                make_float4(acc[i][4], acc[i][5], acc[i][6], acc[i][7]);
        }
    }

    // fused el/er: this block covers heads hA = n0/64 and hB = hA+1 fully.
    int hA = n0 >> 6, hB = hA + 1;
    float alv[8], arv[8];
    #pragma unroll
    for (int j = 0; j < 4; j++) {
        alv[j]   = al [(size_t)p * HH * DD + hA * DD + tx * 4 + j];
        arv[j]   = ar_[(size_t)p * HH * DD + hA * DD + tx * 4 + j];
        alv[4+j] = al [(size_t)p * HH * DD + hB * DD + tx * 4 + j];
        arv[4+j] = ar_[(size_t)p * HH * DD + hB * DD + tx * 4 + j];
    }
    #pragma unroll
    for (int i = 0; i < 8; i++) {
        float pa = 0.f, qa = 0.f, pb = 0.f, qb = 0.f;
        #pragma unroll
        for (int j = 0; j < 4; j++) {
            pa += acc[i][j]   * alv[j];
            qa += acc[i][j]   * arv[j];
            pb += acc[i][4+j] * alv[4+j];
            qb += acc[i][4+j] * arv[4+j];
        }
        // reduce across the 16 tx lanes (lanes 0-15 / 16-31 each one ty)
        #pragma unroll
        for (int off = 1; off < 16; off <<= 1) {
            pa += __shfl_xor_sync(0xffffffffu, pa, off);
            qa += __shfl_xor_sync(0xffffffffu, qa, off);
            pb += __shfl_xor_sync(0xffffffffu, pb, off);
            qb += __shfl_xor_sync(0xffffffffu, qb, off);
        }
        if (tx == 0) {
            int r = m0 + ty * 8 + i;
            if (r < NN) {
                size_t base = ((size_t)p * NN + r) * HH;
                g_el[base + hA] = pa;  g_er[base + hA] = qa;
                g_el[base + hB] = pb;  g_er[base + hB] = qb;
            }
        }
    }
}

// ---------------- CSR build ----------------
__global__ void k_hist(const int* __restrict__ dst) {
    int e = blockIdx.x * blockDim.x + threadIdx.x;
    int p = blockIdx.z;
    if (e < EE) atomicAdd(&g_deg[p * NN + dst[(size_t)p * EE + e]], 1);
}

__device__ __forceinline__ int warp_incl_scan(int v, int lane) {
    #pragma unroll
    for (int off = 1; off < 32; off <<= 1) {
        int t = __shfl_up_sync(0xffffffffu, v, off);
        if (lane >= off) v += t;
    }
    return v;
}

__global__ void k_scan() {
    int p = blockIdx.z;
    __shared__ int wsum[32];
    __shared__ int carry;
    int tid = threadIdx.x;           // 1024 threads
    int lane = tid & 31, wid = tid >> 5;
    if (tid == 0) { carry = 0; g_rowptr[p * (NN + 1)] = 0; }
    __syncthreads();
    for (int base = 0; base < NN; base += 1024) {
        int idx = base + tid;
        int v = (idx < NN) ? g_deg[p * NN + idx] : 0;
        int sc = warp_incl_scan(v, lane);
        if (lane == 31) wsum[wid] = sc;
        __syncthreads();
        if (tid < 32) {
            int s = warp_incl_scan(wsum[tid], tid);
            wsum[tid] = s;
        }
        __syncthreads();
        int pre = (wid > 0) ? wsum[wid - 1] : 0;
        int c = carry;
        int incl = pre + sc;
        if (idx < NN) {
            g_rowptr[p * (NN + 1) + idx + 1] = c + incl;
            g_cur[p * NN + idx] = c + incl - v;
        }
        __syncthreads();
        if (tid == 0) carry = c + wsum[31];
        __syncthreads();
    }
}

__global__ void k_fill(const int* __restrict__ dst) {
    int e = blockIdx.x * blockDim.x + threadIdx.x;
    int p = blockIdx.z;
    if (e >= EE) return;
    int d = dst[(size_t)p * EE + e];
    int pos = atomicAdd(&g_cur[p * NN + d], 1);
    g_eidx[(size_t)p * EE + pos] = e;
}

// ---------------- K5: fused GAT per dst node (warp per node) ----------------
__device__ __forceinline__ float lrelu(float v) { return v > 0.f ? v : SLOPE * v; }

__global__ void __launch_bounds__(256) k_gat(
    int p, const int* __restrict__ src, const float* __restrict__ h,
    float* __restrict__ attn_out) {
    int gw = (blockIdx.x * blockDim.x + threadIdx.x) >> 5;
    int lane = threadIdx.x & 31;
    if (gw >= NN) return;
    int n = gw;
    int beg = g_rowptr[p * (NN + 1) + n];
    int end = g_rowptr[p * (NN + 1) + n + 1];

    float4 er4 = *(const float4*)(g_er + ((size_t)p * NN + n) * HH);

    // pass 1: segment max per head
    float m0 = -1e30f, m1 = -1e30f, m2 = -1e30f, m3 = -1e30f;
    for (int j = beg + lane; j < end; j += 32) {
        int eid = g_eidx[(size_t)p * EE + j];
        int s = src[(size_t)p * EE + eid];
        float4 el4 = *(const float4*)(g_el + ((size_t)p * NN + s) * HH);
        m0 = fmaxf(m0, lrelu(el4.x + er4.x));
        m1 = fmaxf(m1, lrelu(el4.y + er4.y));
        m2 = fmaxf(m2, lrelu(el4.z + er4.z));
        m3 = fmaxf(m3, lrelu(el4.w + er4.w));
    }
    #pragma unroll
    for (int off = 16; off; off >>= 1) {
        m0 = fmaxf(m0, __shfl_xor_sync(0xffffffffu, m0, off));
        m1 = fmaxf(m1, __shfl_xor_sync(0xffffffffu, m1, off));
        m2 = fmaxf(m2, __shfl_xor_sync(0xffffffffu, m2, off));
        m3 = fmaxf(m3, __shfl_xor_sync(0xffffffffu, m3, off));
    }

    // pass 2: denominator
    float d0 = 0.f, d1 = 0.f, d2 = 0.f, d3 = 0.f;
    for (int j = beg + lane; j < end; j += 32) {
        int eid = g_eidx[(size_t)p * EE + j];
        int s = src[(size_t)p * EE + eid];
        float4 el4 = *(const float4*)(g_el + ((size_t)p * NN + s) * HH);
        d0 += __expf(lrelu(el4.x + er4.x) - m0);
        d1 += __expf(lrelu(el4.y + er4.y) - m1);
        d2 += __expf(lrelu(el4.z + er4.z) - m2);
        d3 += __expf(lrelu(el4.w + er4.w) - m3);
    }
    #pragma unroll
    for (int off = 16; off; off >>= 1) {
        d0 += __shfl_xor_sync(0xffffffffu, d0, off);
        d1 += __shfl_xor_sync(0xffffffffu, d1, off);
        d2 += __shfl_xor_sync(0xffffffffu, d2, off);
        d3 += __shfl_xor_sync(0xffffffffu, d3, off);
    }
    float i0 = d0 > 0.f ? 1.f / d0 : 0.f;
    float i1 = d1 > 0.f ? 1.f / d1 : 0.f;
    float i2 = d2 > 0.f ? 1.f / d2 : 0.f;
    float i3 = d3 > 0.f ? 1.f / d3 : 0.f;

    // pass 3: alpha + aggregation
    float4 acc0 = make_float4(0.f, 0.f, 0.f, 0.f);
    float4 acc1 = make_float4(0.f, 0.f, 0.f, 0.f);
    for (int jb = beg; jb < end; jb += 32) {
        int j = jb + lane;
        int sj = 0;
        float a0 = 0.f, a1 = 0.f, a2 = 0.f, a3 = 0.f;
        if (j < end) {
            int eid = g_eidx[(size_t)p * EE + j];
            sj = src[(size_t)p * EE + eid];
            float4 el4 = *(const float4*)(g_el + ((size_t)p * NN + sj) * HH);
            a0 = __expf(lrelu(el4.x + er4.x) - m0) * i0;
            a1 = __expf(lrelu(el4.y + er4.y) - m1) * i1;
            a2 = __expf(lrelu(el4.z + er4.z) - m2) * i2;
            a3 = __expf(lrelu(el4.w + er4.w) - m3) * i3;
            attn_out[(size_t)p * EE + eid] = 0.25f * (a0 + a1 + a2 + a3);
        }
        int cnt = min(32, end - jb);
        for (int t = 0; t < cnt; t++) {
            int s_t  = __shfl_sync(0xffffffffu, sj, t);
            float b0 = __shfl_sync(0xffffffffu, a0, t);
            float b1 = __shfl_sync(0xffffffffu, a1, t);
            float b2 = __shfl_sync(0xffffffffu, a2, t);
            float b3 = __shfl_sync(0xffffffffu, a3, t);
            const float4* fp = (const float4*)(g_feat + ((size_t)p * NN + s_t) * CIN);
            float4 f0 = fp[lane];          // chunks 0..31: heads 0,1
            float4 f1 = fp[lane + 32];     // chunks 32..63: heads 2,3
            float w0 = (lane < 16) ? b0 : b1;
            float w1 = (lane < 16) ? b2 : b3;
            acc0.x += f0.x * w0; acc0.y += f0.y * w0;
            acc0.z += f0.z * w0; acc0.w += f0.w * w0;
            acc1.x += f1.x * w1; acc1.y += f1.y * w1;
            acc1.z += f1.z * w1; acc1.w += f1.w * w1;
        }
    }

    // epilogue: x = relu(out) + h
    const float4* hp = (const float4*)(h + (size_t)n * CIN);
    float4 h0 = hp[lane], h1 = hp[lane + 32];
    float4 x0, x1;
    x0.x = fmaxf(acc0.x, 0.f) + h0.x; x0.y = fmaxf(acc0.y, 0.f) + h0.y;
    x0.z = fmaxf(acc0.z, 0.f) + h0.z; x0.w = fmaxf(acc0.w, 0.f) + h0.w;
    x1.x = fmaxf(acc1.x, 0.f) + h1.x; x1.y = fmaxf(acc1.y, 0.f) + h1.y;
    x1.z = fmaxf(acc1.z, 0.f) + h1.z; x1.w = fmaxf(acc1.w, 0.f) + h1.w;
    float4* op = (float4*)(g_accum + ((size_t)p * NN + n) * CIN);
    op[lane] = x0; op[lane + 32] = x1;
}

// ---------------- K6: BN stats ----------------
#define ROWS_PER_BLOCK 100
__global__ void k_stats() {
    int p = blockIdx.z;
    int c = threadIdx.x;                  // 256 channels
    int r0 = blockIdx.x * ROWS_PER_BLOCK;
    float s = 0.f, q = 0.f;
    for (int r = r0; r < r0 + ROWS_PER_BLOCK; r++) {
        float x = g_accum[((size_t)p * NN + r) * CIN + c];
        s += x; q += x * x;
    }
    atomicAdd(&g_sum[p * CIN + c], s);
    atomicAdd(&g_sumsq[p * CIN + c], q);
}

// ---------------- K7: BN affine ----------------
__global__ void k_bnfin(const float* __restrict__ gamma, const float* __restrict__ beta) {
    int p = blockIdx.z; int c = threadIdx.x;
    float mu  = g_sum[p * CIN + c] * (1.f / NN);
    float var = g_sumsq[p * CIN + c] * (1.f / NN) - mu * mu;
    float sc = gamma[c] * rsqrtf(var + EPS);
    g_scale[p * CIN + c] = sc;
    g_shift[p * CIN + c] = beta[c] - sc * mu;
}

// ---------------- K8: pooled output ----------------
__global__ void k_pool(const float* __restrict__ wmat, float* __restrict__ pooled) {
    int idx = blockIdx.x * blockDim.x + threadIdx.x;   // over N * 64 float4-chunks
    if (idx >= NN * 64) return;
    int n = idx >> 6, c4 = (idx & 63) * 4;
    float4 acc = make_float4(0.f, 0.f, 0.f, 0.f);
    #pragma unroll
    for (int p = 0; p < PP; p++) {
        float wv = wmat[n * PP + p];
        float4 x  = *(const float4*)(g_accum + ((size_t)p * NN + n) * CIN + c4);
        float4 sc = *(const float4*)(g_scale + p * CIN + c4);
        float4 sh = *(const float4*)(g_shift + p * CIN + c4);
        acc.x += wv * (sc.x * x.x + sh.x);
        acc.y += wv * (sc.y * x.y + sh.y);
        acc.z += wv * (sc.z * x.z + sh.z);
        acc.w += wv * (sc.w * x.w + sh.w);
    }
    *(float4*)(pooled + (size_t)n * CIN + c4) = acc;
}

// ---------------- host ----------------
extern "C" void kernel_launch(void* const* d_in, const int* in_sizes, int n_in,
                              void* d_out, int out_size) {
    const float* h     = (const float*)d_in[0];
    const float* mask  = (const float*)d_in[1];
    const int*   src   = (const int*)  d_in[2];
    const int*   dst   = (const int*)  d_in[3];
    const float* fc    = (const float*)d_in[4];
    const float* al    = (const float*)d_in[5];
    const float* ar    = (const float*)d_in[6];
    const float* gamma = (const float*)d_in[7];
    const float* beta  = (const float*)d_in[8];

    float* out    = (float*)d_out;
    float* pooled = out;                              // [N, 256]
    float* wout   = out + (size_t)NN * CIN;           // [N, 3]
    float* attn   = wout + (size_t)NN * PP;           // [3, E]

    k_zero<<<(PP * NN + 255) / 256, 256>>>();
    k_w<<<(NN + 255) / 256, 256>>>(mask, wout);

    dim3 gg(CIN / GN, (NN + GM - 1) / GM, PP);
    k_gemm<<<gg, 256>>>(h, fc, al, ar);

    k_hist<<<dim3((EE + 255) / 256, 1, PP), 256>>>(dst);
    k_scan<<<dim3(1, 1, PP), 1024>>>();
    k_fill<<<dim3((EE + 255) / 256, 1, PP), 256>>>(dst);

    for (int p = 0; p < PP; p++)
        k_gat<<<(NN * 32) / 256, 256>>>(p, src, h, attn);

    k_stats<<<dim3(NN / ROWS_PER_BLOCK, 1, PP), 256>>>();
    k_bnfin<<<dim3(1, 1, PP), 256>>>(gamma, beta);
    k_pool<<<(NN * 64 + 255) / 256, 256>>>(wout, pooled);
}

// round 4
// speedup vs baseline: 1.9691x; 1.3214x over previous
#include <cuda_runtime.h>
#include <cuda_bf16.h>
#include <cstdint>

#define NN   50000
#define EE   800000
#define PP   3
#define HH   4
#define DD   64
#define CIN  256          // H*D = in_size
#define K2   512          // split-K (hi|lo concat)
#define EPS  1e-5f
#define SLOPE 0.2f

// ---------------- device scratch (static, no allocation) ----------------
__device__ __align__(256) float g_feat [(size_t)PP*NN*CIN];   // projected features per path
__device__ __align__(256) float g_accum[(size_t)PP*NN*CIN];   // x = relu(out)+h per path
__device__ __align__(256) __nv_bfloat16 g_h2 [(size_t)NN*K2];        // h split: hi | lo along K
__device__ __align__(256) __nv_bfloat16 g_w2t[(size_t)PP*CIN*K2];    // W^T split: [p][n][k] hi|lo
__device__ __align__(16)  float g_el   [PP*NN*HH];
__device__ __align__(16)  float g_er   [PP*NN*HH];
__device__ int g_deg   [PP*NN];
__device__ int g_rowptr[PP*(NN+1)];
__device__ int g_cur   [PP*NN];
__device__ int g_eidx  [(size_t)PP*EE];
__device__ float g_sum  [PP*CIN];
__device__ float g_sumsq[PP*CIN];
__device__ float g_scale[PP*CIN];
__device__ float g_shift[PP*CIN];

// ---------------- K0: zero small scratch ----------------
__global__ void k_zero() {
    int i = blockIdx.x * blockDim.x + threadIdx.x;
    if (i < PP * NN) g_deg[i] = 0;
    if (i < PP * CIN) { g_sum[i] = 0.f; g_sumsq[i] = 0.f; }
}

// ---------------- Kw: semantic weights ----------------
__global__ void k_w(const float* __restrict__ mask, float* __restrict__ wout) {
    int n = blockIdx.x * blockDim.x + threadIdx.x;
    if (n >= NN) return;
    float m0 = mask[n*PP+0], m1 = mask[n*PP+1], m2 = mask[n*PP+2];
    float inv = 1.f / (m0 + m1 + m2);
    wout[n*PP+0] = m0 * inv;
    wout[n*PP+1] = m1 * inv;
    wout[n*PP+2] = m2 * inv;
}

// ---------------- conversions: fp32 -> bf16 hi/lo split ----------------
__global__ void k_cvt_h(const float* __restrict__ h) {
    size_t i = (size_t)blockIdx.x * blockDim.x + threadIdx.x;
    if (i >= (size_t)NN * CIN) return;
    size_t m = i >> 8, k = i & 255;
    float v = h[i];
    __nv_bfloat16 hi = __float2bfloat16(v);
    __nv_bfloat16 lo = __float2bfloat16(v - __bfloat162float(hi));
    g_h2[m * K2 + k]       = hi;
    g_h2[m * K2 + 256 + k] = lo;
}
__global__ void k_cvt_w(const float* __restrict__ fc) {
    int i = blockIdx.x * blockDim.x + threadIdx.x;
    if (i >= PP * CIN * CIN) return;
    int p = i >> 16, rem = i & 65535;
    int k = rem >> 8, n = rem & 255;
    float v = fc[i];
    __nv_bfloat16 hi = __float2bfloat16(v);
    __nv_bfloat16 lo = __float2bfloat16(v - __bfloat162float(hi));
    size_t base = ((size_t)p * CIN + n) * K2;
    g_w2t[base + k]       = hi;
    g_w2t[base + 256 + k] = lo;
}

// ---------------- K1: HMMA bf16 split GEMM + fused el/er ----------------
// 128x128 block tile, 8 warps (4 M x 2 N), warp tile 32x64, BK=64, K2=512.
// mma.sync m16n8k16 row.col, fragments loaded with plain LDS from padded smem.
#define BKK 64
#define ASTR 72          // padded row stride in bf16 (144 B -> conflict-free frag loads)

__device__ __forceinline__ void mma_bf16(float* c, const uint32_t* a, const uint32_t* b) {
    asm volatile("mma.sync.aligned.m16n8k16.row.col.f32.bf16.bf16.f32 "
        "{%0,%1,%2,%3}, {%4,%5,%6,%7}, {%8,%9}, {%0,%1,%2,%3};"
        : "+f"(c[0]), "+f"(c[1]), "+f"(c[2]), "+f"(c[3])
        : "r"(a[0]), "r"(a[1]), "r"(a[2]), "r"(a[3]), "r"(b[0]), "r"(b[1]));
}

__global__ void __launch_bounds__(256, 2) k_mma(
    const float* __restrict__ al, const float* __restrict__ ar_) {
    __shared__ __nv_bfloat16 sA[128 * ASTR];
    __shared__ __nv_bfloat16 sB[128 * ASTR];

    int p = blockIdx.z;
    int m0 = blockIdx.y * 128, n0 = blockIdx.x * 128;
    int tid = threadIdx.x, wid = tid >> 5, lane = tid & 31;
    int wm = wid & 3, wn = wid >> 2;     // warp rows wm*32, cols wn*64
    int grp = lane >> 2, tg = lane & 3;

    float acc[2][8][4];
    #pragma unroll
    for (int ms = 0; ms < 2; ms++)
        #pragma unroll
        for (int nt = 0; nt < 8; nt++)
            #pragma unroll
            for (int q = 0; q < 4; q++) acc[ms][nt][q] = 0.f;

    const uint4 zero4 = make_uint4(0u, 0u, 0u, 0u);
    for (int kb = 0; kb < K2 / BKK; kb++) {
        // load A & B k-block: 128 rows x 64 bf16 each (8 x 16B segs/row)
        #pragma unroll
        for (int t = 0; t < 4; t++) {
            int c = tid + t * 256;            // 0..1023
            int row = c >> 3, seg = c & 7;
            int gm = m0 + row;
            uint4 va = (gm < NN)
                ? *(const uint4*)(g_h2 + (size_t)gm * K2 + kb * BKK + seg * 8) : zero4;
            *(uint4*)(sA + row * ASTR + seg * 8) = va;
            uint4 vb = *(const uint4*)(g_w2t + ((size_t)p * CIN + n0 + row) * K2 + kb * BKK + seg * 8);
            *(uint4*)(sB + row * ASTR + seg * 8) = vb;
        }
        __syncthreads();

        #pragma unroll
        for (int ks = 0; ks < BKK / 16; ks++) {
            int k0 = ks * 16;
            uint32_t afr[2][4];
            #pragma unroll
            for (int ms = 0; ms < 2; ms++) {
                int r = wm * 32 + ms * 16;
                afr[ms][0] = *(const uint32_t*)(sA + (r + grp)     * ASTR + k0 + tg * 2);
                afr[ms][1] = *(const uint32_t*)(sA + (r + grp + 8) * ASTR + k0 + tg * 2);
                afr[ms][2] = *(const uint32_t*)(sA + (r + grp)     * ASTR + k0 + tg * 2 + 8);
                afr[ms][3] = *(const uint32_t*)(sA + (r + grp + 8) * ASTR + k0 + tg * 2 + 8);
            }
            uint32_t bfr[8][2];
            #pragma unroll
            for (int nt = 0; nt < 8; nt++) {
                int nr = wn * 64 + nt * 8 + grp;
                bfr[nt][0] = *(const uint32_t*)(sB + nr * ASTR + k0 + tg * 2);
                bfr[nt][1] = *(const uint32_t*)(sB + nr * ASTR + k0 + tg * 2 + 8);
            }
            #pragma unroll
            for (int ms = 0; ms < 2; ms++)
                #pragma unroll
                for (int nt = 0; nt < 8; nt++)
                    mma_bf16(acc[ms][nt], afr[ms], bfr[nt]);
        }
        __syncthreads();
    }

    // epilogue: store feat + fused el/er (warp tile spans exactly one head)
    int head = (n0 >> 6) + wn;
    float alv[16], arv[16];
    #pragma unroll
    for (int nt = 0; nt < 8; nt++) {
        int d = nt * 8 + tg * 2;
        alv[nt*2+0] = al [(size_t)p * CIN + head * DD + d];
        alv[nt*2+1] = al [(size_t)p * CIN + head * DD + d + 1];
        arv[nt*2+0] = ar_[(size_t)p * CIN + head * DD + d];
        arv[nt*2+1] = ar_[(size_t)p * CIN + head * DD + d + 1];
    }

    #pragma unroll
    for (int ms = 0; ms < 2; ms++) {
        int r0 = m0 + wm * 32 + ms * 16 + grp;
        int r1 = r0 + 8;
        float el0 = 0.f, er0 = 0.f, el1 = 0.f, er1 = 0.f;
        #pragma unroll
        for (int nt = 0; nt < 8; nt++) {
            float c0 = acc[ms][nt][0], c1 = acc[ms][nt][1];
            float c2 = acc[ms][nt][2], c3 = acc[ms][nt][3];
            el0 += c0 * alv[nt*2] + c1 * alv[nt*2+1];
            er0 += c0 * arv[nt*2] + c1 * arv[nt*2+1];
            el1 += c2 * alv[nt*2] + c3 * alv[nt*2+1];
            er1 += c2 * arv[nt*2] + c3 * arv[nt*2+1];
            int col = n0 + wn * 64 + nt * 8 + tg * 2;
            if (r0 < NN)
                *(float2*)(g_feat + ((size_t)p * NN + r0) * CIN + col) = make_float2(c0, c1);
            if (r1 < NN)
                *(float2*)(g_feat + ((size_t)p * NN + r1) * CIN + col) = make_float2(c2, c3);
        }
        // reduce across the 4 quad lanes (same row, different cols)
        #pragma unroll
        for (int off = 1; off < 4; off <<= 1) {
            el0 += __shfl_xor_sync(0xffffffffu, el0, off);
            er0 += __shfl_xor_sync(0xffffffffu, er0, off);
            el1 += __shfl_xor_sync(0xffffffffu, el1, off);
            er1 += __shfl_xor_sync(0xffffffffu, er1, off);
        }
        if (tg == 0) {
            if (r0 < NN) {
                g_el[((size_t)p * NN + r0) * HH + head] = el0;
                g_er[((size_t)p * NN + r0) * HH + head] = er0;
            }
            if (r1 < NN) {
                g_el[((size_t)p * NN + r1) * HH + head] = el1;
                g_er[((size_t)p * NN + r1) * HH + head] = er1;
            }
        }
    }
}

// ---------------- CSR build ----------------
__global__ void k_hist(const int* __restrict__ dst) {
    int e = blockIdx.x * blockDim.x + threadIdx.x;
    int p = blockIdx.z;
    if (e < EE) atomicAdd(&g_deg[p * NN + dst[(size_t)p * EE + e]], 1);
}

__device__ __forceinline__ int warp_incl_scan(int v, int lane) {
    #pragma unroll
    for (int off = 1; off < 32; off <<= 1) {
        int t = __shfl_up_sync(0xffffffffu, v, off);
        if (lane >= off) v += t;
    }
    return v;
}

__global__ void k_scan() {
    int p = blockIdx.z;
    __shared__ int wsum[32];
    __shared__ int carry;
    int tid = threadIdx.x;           // 1024 threads
    int lane = tid & 31, wid = tid >> 5;
    if (tid == 0) { carry = 0; g_rowptr[p * (NN + 1)] = 0; }
    __syncthreads();
    for (int base = 0; base < NN; base += 1024) {
        int idx = base + tid;
        int v = (idx < NN) ? g_deg[p * NN + idx] : 0;
        int sc = warp_incl_scan(v, lane);
        if (lane == 31) wsum[wid] = sc;
        __syncthreads();
        if (tid < 32) {
            int s = warp_incl_scan(wsum[tid], tid);
            wsum[tid] = s;
        }
        __syncthreads();
        int pre = (wid > 0) ? wsum[wid - 1] : 0;
        int c = carry;
        int incl = pre + sc;
        if (idx < NN) {
            g_rowptr[p * (NN + 1) + idx + 1] = c + incl;
            g_cur[p * NN + idx] = c + incl - v;
        }
        __syncthreads();
        if (tid == 0) carry = c + wsum[31];
        __syncthreads();
    }
}

__global__ void k_fill(const int* __restrict__ dst) {
    int e = blockIdx.x * blockDim.x + threadIdx.x;
    int p = blockIdx.z;
    if (e >= EE) return;
    int d = dst[(size_t)p * EE + e];
    int pos = atomicAdd(&g_cur[p * NN + d], 1);
    g_eidx[(size_t)p * EE + pos] = e;
}

// ---------------- K5: fused GAT per dst node (warp per node) ----------------
__device__ __forceinline__ float lrelu(float v) { return v > 0.f ? v : SLOPE * v; }

__global__ void __launch_bounds__(256) k_gat(
    int p, const int* __restrict__ src, const float* __restrict__ h,
    float* __restrict__ attn_out) {
    int gw = (blockIdx.x * blockDim.x + threadIdx.x) >> 5;
    int lane = threadIdx.x & 31;
    if (gw >= NN) return;
    int n = gw;
    int beg = g_rowptr[p * (NN + 1) + n];
    int end = g_rowptr[p * (NN + 1) + n + 1];

    float4 er4 = *(const float4*)(g_er + ((size_t)p * NN + n) * HH);

    // pass 1: segment max per head
    float m0 = -1e30f, m1 = -1e30f, m2 = -1e30f, m3 = -1e30f;
    for (int j = beg + lane; j < end; j += 32) {
        int eid = g_eidx[(size_t)p * EE + j];
        int s = src[(size_t)p * EE + eid];
        float4 el4 = *(const float4*)(g_el + ((size_t)p * NN + s) * HH);
        m0 = fmaxf(m0, lrelu(el4.x + er4.x));
        m1 = fmaxf(m1, lrelu(el4.y + er4.y));
        m2 = fmaxf(m2, lrelu(el4.z + er4.z));
        m3 = fmaxf(m3, lrelu(el4.w + er4.w));
    }
    #pragma unroll
    for (int off = 16; off; off >>= 1) {
        m0 = fmaxf(m0, __shfl_xor_sync(0xffffffffu, m0, off));
        m1 = fmaxf(m1, __shfl_xor_sync(0xffffffffu, m1, off));
        m2 = fmaxf(m2, __shfl_xor_sync(0xffffffffu, m2, off));
        m3 = fmaxf(m3, __shfl_xor_sync(0xffffffffu, m3, off));
    }

    // pass 2: denominator
    float d0 = 0.f, d1 = 0.f, d2 = 0.f, d3 = 0.f;
    for (int j = beg + lane; j < end; j += 32) {
        int eid = g_eidx[(size_t)p * EE + j];
        int s = src[(size_t)p * EE + eid];
        float4 el4 = *(const float4*)(g_el + ((size_t)p * NN + s) * HH);
        d0 += __expf(lrelu(el4.x + er4.x) - m0);
        d1 += __expf(lrelu(el4.y + er4.y) - m1);
        d2 += __expf(lrelu(el4.z + er4.z) - m2);
        d3 += __expf(lrelu(el4.w + er4.w) - m3);
    }
    #pragma unroll
    for (int off = 16; off; off >>= 1) {
        d0 += __shfl_xor_sync(0xffffffffu, d0, off);
        d1 += __shfl_xor_sync(0xffffffffu, d1, off);
        d2 += __shfl_xor_sync(0xffffffffu, d2, off);
        d3 += __shfl_xor_sync(0xffffffffu, d3, off);
    }
    float i0 = d0 > 0.f ? 1.f / d0 : 0.f;
    float i1 = d1 > 0.f ? 1.f / d1 : 0.f;
    float i2 = d2 > 0.f ? 1.f / d2 : 0.f;
    float i3 = d3 > 0.f ? 1.f / d3 : 0.f;

    // pass 3: alpha + aggregation
    float4 acc0 = make_float4(0.f, 0.f, 0.f, 0.f);
    float4 acc1 = make_float4(0.f, 0.f, 0.f, 0.f);
    for (int jb = beg; jb < end; jb += 32) {
        int j = jb + lane;
        int sj = 0;
        float a0 = 0.f, a1 = 0.f, a2 = 0.f, a3 = 0.f;
        if (j < end) {
            int eid = g_eidx[(size_t)p * EE + j];
            sj = src[(size_t)p * EE + eid];
            float4 el4 = *(const float4*)(g_el + ((size_t)p * NN + sj) * HH);
            a0 = __expf(lrelu(el4.x + er4.x) - m0) * i0;
            a1 = __expf(lrelu(el4.y + er4.y) - m1) * i1;
            a2 = __expf(lrelu(el4.z + er4.z) - m2) * i2;
            a3 = __expf(lrelu(el4.w + er4.w) - m3) * i3;
            attn_out[(size_t)p * EE + eid] = 0.25f * (a0 + a1 + a2 + a3);
        }
        int cnt = min(32, end - jb);
        for (int t = 0; t < cnt; t++) {
            int s_t  = __shfl_sync(0xffffffffu, sj, t);
            float b0 = __shfl_sync(0xffffffffu, a0, t);
            float b1 = __shfl_sync(0xffffffffu, a1, t);
            float b2 = __shfl_sync(0xffffffffu, a2, t);
            float b3 = __shfl_sync(0xffffffffu, a3, t);
            const float4* fp = (const float4*)(g_feat + ((size_t)p * NN + s_t) * CIN);
            float4 f0 = fp[lane];          // chunks 0..31: heads 0,1
            float4 f1 = fp[lane + 32];     // chunks 32..63: heads 2,3
            float w0 = (lane < 16) ? b0 : b1;
            float w1 = (lane < 16) ? b2 : b3;
            acc0.x += f0.x * w0; acc0.y += f0.y * w0;
            acc0.z += f0.z * w0; acc0.w += f0.w * w0;
            acc1.x += f1.x * w1; acc1.y += f1.y * w1;
            acc1.z += f1.z * w1; acc1.w += f1.w * w1;
        }
    }

    // epilogue: x = relu(out) + h
    const float4* hp = (const float4*)(h + (size_t)n * CIN);
    float4 h0 = hp[lane], h1 = hp[lane + 32];
    float4 x0, x1;
    x0.x = fmaxf(acc0.x, 0.f) + h0.x; x0.y = fmaxf(acc0.y, 0.f) + h0.y;
    x0.z = fmaxf(acc0.z, 0.f) + h0.z; x0.w = fmaxf(acc0.w, 0.f) + h0.w;
    x1.x = fmaxf(acc1.x, 0.f) + h1.x; x1.y = fmaxf(acc1.y, 0.f) + h1.y;
    x1.z = fmaxf(acc1.z, 0.f) + h1.z; x1.w = fmaxf(acc1.w, 0.f) + h1.w;
    float4* op = (float4*)(g_accum + ((size_t)p * NN + n) * CIN);
    op[lane] = x0; op[lane + 32] = x1;
}

// ---------------- K6: BN stats ----------------
#define ROWS_PER_BLOCK 100
__global__ void k_stats() {
    int p = blockIdx.z;
    int c = threadIdx.x;                  // 256 channels
    int r0 = blockIdx.x * ROWS_PER_BLOCK;
    float s = 0.f, q = 0.f;
    for (int r = r0; r < r0 + ROWS_PER_BLOCK; r++) {
        float x = g_accum[((size_t)p * NN + r) * CIN + c];
        s += x; q += x * x;
    }
    atomicAdd(&g_sum[p * CIN + c], s);
    atomicAdd(&g_sumsq[p * CIN + c], q);
}

// ---------------- K7: BN affine ----------------
__global__ void k_bnfin(const float* __restrict__ gamma, const float* __restrict__ beta) {
    int p = blockIdx.z; int c = threadIdx.x;
    float mu  = g_sum[p * CIN + c] * (1.f / NN);
    float var = g_sumsq[p * CIN + c] * (1.f / NN) - mu * mu;
    float sc = gamma[c] * rsqrtf(var + EPS);
    g_scale[p * CIN + c] = sc;
    g_shift[p * CIN + c] = beta[c] - sc * mu;
}

// ---------------- K8: pooled output ----------------
__global__ void k_pool(const float* __restrict__ wmat, float* __restrict__ pooled) {
    int idx = blockIdx.x * blockDim.x + threadIdx.x;   // over N * 64 float4-chunks
    if (idx >= NN * 64) return;
    int n = idx >> 6, c4 = (idx & 63) * 4;
    float4 acc = make_float4(0.f, 0.f, 0.f, 0.f);
    #pragma unroll
    for (int p = 0; p < PP; p++) {
        float wv = wmat[n * PP + p];
        float4 x  = *(const float4*)(g_accum + ((size_t)p * NN + n) * CIN + c4);
        float4 sc = *(const float4*)(g_scale + p * CIN + c4);
        float4 sh = *(const float4*)(g_shift + p * CIN + c4);
        acc.x += wv * (sc.x * x.x + sh.x);
        acc.y += wv * (sc.y * x.y + sh.y);
        acc.z += wv * (sc.z * x.z + sh.z);
        acc.w += wv * (sc.w * x.w + sh.w);
    }
    *(float4*)(pooled + (size_t)n * CIN + c4) = acc;
}

// ---------------- host ----------------
extern "C" void kernel_launch(void* const* d_in, const int* in_sizes, int n_in,
                              void* d_out, int out_size) {
    const float* h     = (const float*)d_in[0];
    const float* mask  = (const float*)d_in[1];
    const int*   src   = (const int*)  d_in[2];
    const int*   dst   = (const int*)  d_in[3];
    const float* fc    = (const float*)d_in[4];
    const float* al    = (const float*)d_in[5];
    const float* ar    = (const float*)d_in[6];
    const float* gamma = (const float*)d_in[7];
    const float* beta  = (const float*)d_in[8];

    float* out    = (float*)d_out;
    float* pooled = out;                              // [N, 256]
    float* wout   = out + (size_t)NN * CIN;           // [N, 3]
    float* attn   = wout + (size_t)NN * PP;           // [3, E]

    k_zero<<<(PP * NN + 255) / 256, 256>>>();
    k_w<<<(NN + 255) / 256, 256>>>(mask, wout);

    k_cvt_h<<<(int)(((size_t)NN * CIN + 255) / 256), 256>>>(h);
    k_cvt_w<<<(PP * CIN * CIN + 255) / 256, 256>>>(fc);

    dim3 gm(CIN / 128, (NN + 127) / 128, PP);
    k_mma<<<gm, 256>>>(al, ar);

    k_hist<<<dim3((EE + 255) / 256, 1, PP), 256>>>(dst);
    k_scan<<<dim3(1, 1, PP), 1024>>>();
    k_fill<<<dim3((EE + 255) / 256, 1, PP), 256>>>(dst);

    for (int p = 0; p < PP; p++)
        k_gat<<<(NN * 32) / 256, 256>>>(p, src, h, attn);

    k_stats<<<dim3(NN / ROWS_PER_BLOCK, 1, PP), 256>>>();
    k_bnfin<<<dim3(1, 1, PP), 256>>>(gamma, beta);
    k_pool<<<(NN * 64 + 255) / 256, 256>>>(wout, pooled);
}

// round 6
// speedup vs baseline: 2.0303x; 1.0311x over previous
#include <cuda_runtime.h>
#include <cuda_bf16.h>
#include <cstdint>

#define NN   50000
#define EE   800000
#define PP   3
#define HH   4
#define DD   64
#define CIN  256          // H*D = in_size
#define K2   512          // split-K (hi|lo concat)
#define EPS  1e-5f
#define SLOPE 0.2f

// ---------------- device scratch (static, no allocation) ----------------
__device__ __align__(256) float g_feat [(size_t)PP*NN*CIN];
__device__ __align__(256) float g_accum[(size_t)PP*NN*CIN];
__device__ __align__(256) __nv_bfloat16 g_h2 [(size_t)NN*K2];
__device__ __align__(256) __nv_bfloat16 g_w2t[(size_t)PP*CIN*K2];
__device__ __align__(16)  float g_el   [PP*NN*HH];
__device__ __align__(16)  float g_er   [PP*NN*HH];
__device__ int g_deg   [PP*NN];
__device__ int g_rowptr[PP*(NN+1)];
__device__ int g_cur   [PP*NN];
__device__ int g_bsum  [PP*64];
__device__ int g_boff  [PP*64];
__device__ int g_eidx  [(size_t)PP*EE];
__device__ int g_esrc  [(size_t)PP*EE];
__device__ float g_sum  [PP*CIN];
__device__ float g_sumsq[PP*CIN];
__device__ float g_scale[PP*CIN];
__device__ float g_shift[PP*CIN];

// ---------------- K0: zero small scratch ----------------
__global__ void k_zero() {
    int i = blockIdx.x * blockDim.x + threadIdx.x;
    if (i < PP * NN) g_deg[i] = 0;
    if (i < PP * CIN) { g_sum[i] = 0.f; g_sumsq[i] = 0.f; }
}

// ---------------- Kw: semantic weights ----------------
__global__ void k_w(const float* __restrict__ mask, float* __restrict__ wout) {
    int n = blockIdx.x * blockDim.x + threadIdx.x;
    if (n >= NN) return;
    float m0 = mask[n*PP+0], m1 = mask[n*PP+1], m2 = mask[n*PP+2];
    float inv = 1.f / (m0 + m1 + m2);
    wout[n*PP+0] = m0 * inv;
    wout[n*PP+1] = m1 * inv;
    wout[n*PP+2] = m2 * inv;
}

// ---------------- conversions: fp32 -> bf16 hi/lo split ----------------
__global__ void k_cvt_h(const float* __restrict__ h) {
    size_t i = (size_t)blockIdx.x * blockDim.x + threadIdx.x;
    if (i >= (size_t)NN * CIN) return;
    size_t m = i >> 8, k = i & 255;
    float v = h[i];
    __nv_bfloat16 hi = __float2bfloat16(v);
    __nv_bfloat16 lo = __float2bfloat16(v - __bfloat162float(hi));
    g_h2[m * K2 + k]       = hi;
    g_h2[m * K2 + 256 + k] = lo;
}
__global__ void k_cvt_w(const float* __restrict__ fc) {
    int i = blockIdx.x * blockDim.x + threadIdx.x;
    if (i >= PP * CIN * CIN) return;
    int p = i >> 16, rem = i & 65535;
    int k = rem >> 8, n = rem & 255;
    float v = fc[i];
    __nv_bfloat16 hi = __float2bfloat16(v);
    __nv_bfloat16 lo = __float2bfloat16(v - __bfloat162float(hi));
    size_t base = ((size_t)p * CIN + n) * K2;
    g_w2t[base + k]       = hi;
    g_w2t[base + 256 + k] = lo;
}

// ---------------- K1: HMMA bf16 split GEMM, cp.async double-buffered ----------------
#define BKK 64
#define ASTR 72                         // bf16 units; 144 B row stride
#define SZA (128 * ASTR * 2)            // 18432 B per tile
#define BUFB (2 * SZA)                  // A + B per buffer
#define SMTOT (2 * BUFB)                // 73728 B

__device__ __forceinline__ void mma_bf16(float* c, const uint32_t* a, const uint32_t* b) {
    asm volatile("mma.sync.aligned.m16n8k16.row.col.f32.bf16.bf16.f32 "
        "{%0,%1,%2,%3}, {%4,%5,%6,%7}, {%8,%9}, {%0,%1,%2,%3};"
        : "+f"(c[0]), "+f"(c[1]), "+f"(c[2]), "+f"(c[3])
        : "r"(a[0]), "r"(a[1]), "r"(a[2]), "r"(a[3]), "r"(b[0]), "r"(b[1]));
}
__device__ __forceinline__ void cp16(uint32_t dst, const void* src, bool valid) {
    int sz = valid ? 16 : 0;
    asm volatile("cp.async.cg.shared.global [%0], [%1], 16, %2;"
                 :: "r"(dst), "l"(src), "r"(sz));
}
__device__ __forceinline__ uint32_t cvta_s(const void* p) {
    uint32_t a;
    asm("{ .reg .u64 t; cvta.to.shared.u64 t, %1; cvt.u32.u64 %0, t; }" : "=r"(a) : "l"(p));
    return a;
}

__global__ void __launch_bounds__(256, 2) k_mma(
    const float* __restrict__ al, const float* __restrict__ ar_) {
    extern __shared__ __align__(16) char dsm[];
    uint32_t sm0 = cvta_s(dsm);

    int p = blockIdx.z;
    int m0 = blockIdx.y * 128, n0 = blockIdx.x * 128;
    int tid = threadIdx.x, wid = tid >> 5, lane = tid & 31;
    int wm = wid & 3, wn = wid >> 2;
    int grp = lane >> 2, tg = lane & 3;

    float acc[2][8][4];
    #pragma unroll
    for (int ms = 0; ms < 2; ms++)
        #pragma unroll
        for (int nt = 0; nt < 8; nt++)
            #pragma unroll
            for (int q = 0; q < 4; q++) acc[ms][nt][q] = 0.f;

    // loader: issue 8 cp.asyncs for tile kb into buffer buf
    auto load_tile = [&](int kb, int buf) {
        uint32_t base = sm0 + buf * BUFB;
        #pragma unroll
        for (int t = 0; t < 4; t++) {
            int c = tid + t * 256;
            int row = c >> 3, seg = c & 7;
            int gm = m0 + row;
            cp16(base + row * 144 + seg * 16,
                 g_h2 + (size_t)gm * K2 + kb * BKK + seg * 8, gm < NN);
            cp16(base + SZA + row * 144 + seg * 16,
                 g_w2t + ((size_t)p * CIN + n0 + row) * K2 + kb * BKK + seg * 8, true);
        }
    };

    load_tile(0, 0);
    asm volatile("cp.async.commit_group;");

    for (int kb = 0; kb < K2 / BKK; kb++) {
        if (kb + 1 < K2 / BKK) load_tile(kb + 1, (kb + 1) & 1);
        asm volatile("cp.async.commit_group;");
        asm volatile("cp.async.wait_group 1;");
        __syncthreads();

        const __nv_bfloat16* sA = (const __nv_bfloat16*)(dsm + (kb & 1) * BUFB);
        const __nv_bfloat16* sB = (const __nv_bfloat16*)(dsm + (kb & 1) * BUFB + SZA);

        #pragma unroll
        for (int ks = 0; ks < BKK / 16; ks++) {
            int k0 = ks * 16;
            uint32_t afr[2][4];
            #pragma unroll
            for (int ms = 0; ms < 2; ms++) {
                int r = wm * 32 + ms * 16;
                afr[ms][0] = *(const uint32_t*)(sA + (r + grp)     * ASTR + k0 + tg * 2);
                afr[ms][1] = *(const uint32_t*)(sA + (r + grp + 8) * ASTR + k0 + tg * 2);
                afr[ms][2] = *(const uint32_t*)(sA + (r + grp)     * ASTR + k0 + tg * 2 + 8);
                afr[ms][3] = *(const uint32_t*)(sA + (r + grp + 8) * ASTR + k0 + tg * 2 + 8);
            }
            uint32_t bfr[8][2];
            #pragma unroll
            for (int nt = 0; nt < 8; nt++) {
                int nr = wn * 64 + nt * 8 + grp;
                bfr[nt][0] = *(const uint32_t*)(sB + nr * ASTR + k0 + tg * 2);
                bfr[nt][1] = *(const uint32_t*)(sB + nr * ASTR + k0 + tg * 2 + 8);
            }
            #pragma unroll
            for (int ms = 0; ms < 2; ms++)
                #pragma unroll
                for (int nt = 0; nt < 8; nt++)
                    mma_bf16(acc[ms][nt], afr[ms], bfr[nt]);
        }
        __syncthreads();
    }

    // epilogue: store feat + fused el/er (warp tile spans exactly one head)
    int head = (n0 >> 6) + wn;
    float alv[16], arv[16];
    #pragma unroll
    for (int nt = 0; nt < 8; nt++) {
        int d = nt * 8 + tg * 2;
        alv[nt*2+0] = al [(size_t)p * CIN + head * DD + d];
        alv[nt*2+1] = al [(size_t)p * CIN + head * DD + d + 1];
        arv[nt*2+0] = ar_[(size_t)p * CIN + head * DD + d];
        arv[nt*2+1] = ar_[(size_t)p * CIN + head * DD + d + 1];
    }
    #pragma unroll
    for (int ms = 0; ms < 2; ms++) {
        int r0 = m0 + wm * 32 + ms * 16 + grp;
        int r1 = r0 + 8;
        float el0 = 0.f, er0 = 0.f, el1 = 0.f, er1 = 0.f;
        #pragma unroll
        for (int nt = 0; nt < 8; nt++) {
            float c0 = acc[ms][nt][0], c1 = acc[ms][nt][1];
            float c2 = acc[ms][nt][2], c3 = acc[ms][nt][3];
            el0 += c0 * alv[nt*2] + c1 * alv[nt*2+1];
            er0 += c0 * arv[nt*2] + c1 * arv[nt*2+1];
            el1 += c2 * alv[nt*2] + c3 * alv[nt*2+1];
            er1 += c2 * arv[nt*2] + c3 * arv[nt*2+1];
            int col = n0 + wn * 64 + nt * 8 + tg * 2;
            if (r0 < NN)
                *(float2*)(g_feat + ((size_t)p * NN + r0) * CIN + col) = make_float2(c0, c1);
            if (r1 < NN)
                *(float2*)(g_feat + ((size_t)p * NN + r1) * CIN + col) = make_float2(c2, c3);
        }
        #pragma unroll
        for (int off = 1; off < 4; off <<= 1) {
            el0 += __shfl_xor_sync(0xffffffffu, el0, off);
            er0 += __shfl_xor_sync(0xffffffffu, er0, off);
            el1 += __shfl_xor_sync(0xffffffffu, el1, off);
            er1 += __shfl_xor_sync(0xffffffffu, er1, off);
        }
        if (tg == 0) {
            if (r0 < NN) {
                g_el[((size_t)p * NN + r0) * HH + head] = el0;
                g_er[((size_t)p * NN + r0) * HH + head] = er0;
            }
            if (r1 < NN) {
                g_el[((size_t)p * NN + r1) * HH + head] = el1;
                g_er[((size_t)p * NN + r1) * HH + head] = er1;
            }
        }
    }
}

// ---------------- CSR build ----------------
__global__ void k_hist(const int* __restrict__ dst) {
    int e = blockIdx.x * blockDim.x + threadIdx.x;
    int p = blockIdx.z;
    if (e < EE) atomicAdd(&g_deg[p * NN + dst[(size_t)p * EE + e]], 1);
}

__device__ __forceinline__ int warp_incl_scan(int v, int lane) {
    #pragma unroll
    for (int off = 1; off < 32; off <<= 1) {
        int t = __shfl_up_sync(0xffffffffu, v, off);
        if (lane >= off) v += t;
    }
    return v;
}

// phase A: per-block (1024 nodes) degree sums
__global__ void k_scanA() {
    int p = blockIdx.z, b = blockIdx.x, tid = threadIdx.x;
    int lane = tid & 31, wid = tid >> 5;
    __shared__ int ws[32];
    int idx = b * 1024 + tid;
    int v = (idx < NN) ? g_deg[p * NN + idx] : 0;
    #pragma unroll
    for (int off = 16; off; off >>= 1) v += __shfl_xor_sync(0xffffffffu, v, off);
    if (lane == 0) ws[wid] = v;
    __syncthreads();
    if (wid == 0) {
        int s = ws[lane];
        #pragma unroll
        for (int off = 16; off; off >>= 1) s += __shfl_xor_sync(0xffffffffu, s, off);
        if (lane == 0) g_bsum[p * 64 + b] = s;
    }
}
// phase B: scan the 49 block sums
__global__ void k_scanB() {
    int p = blockIdx.z, tid = threadIdx.x;   // 64 threads
    int lane = tid & 31, w = tid >> 5;
    __shared__ int t0;
    int v = (tid < 49) ? g_bsum[p * 64 + tid] : 0;
    int sc = warp_incl_scan(v, lane);
    if (w == 0 && lane == 31) t0 = sc;
    __syncthreads();
    int incl = sc + (w == 1 ? t0 : 0);
    g_boff[p * 64 + tid] = incl - v;         // exclusive prefix
}
// phase C: full per-block scan + apply offset
__global__ void k_scanC() {
    int p = blockIdx.z, b = blockIdx.x, tid = threadIdx.x;
    int lane = tid & 31, wid = tid >> 5;
    __shared__ int ws[32];
    int idx = b * 1024 + tid;
    int v = (idx < NN) ? g_deg[p * NN + idx] : 0;
    int sc = warp_incl_scan(v, lane);
    if (lane == 31) ws[wid] = sc;
    __syncthreads();
    if (wid == 0) ws[lane] = warp_incl_scan(ws[lane], lane);
    __syncthreads();
    int incl = sc + (wid > 0 ? ws[wid - 1] : 0) + g_boff[p * 64 + b];
    if (idx < NN) {
        g_rowptr[p * (NN + 1) + idx + 1] = incl;
        g_cur[p * NN + idx] = incl - v;
    }
    if (b == 0 && tid == 0) g_rowptr[p * (NN + 1)] = 0;
}

__global__ void k_fill(const int* __restrict__ dst, const int* __restrict__ src) {
    int e = blockIdx.x * blockDim.x + threadIdx.x;
    int p = blockIdx.z;
    if (e >= EE) return;
    int d = dst[(size_t)p * EE + e];
    int pos = atomicAdd(&g_cur[p * NN + d], 1);
    g_eidx[(size_t)p * EE + pos] = e;
    g_esrc[(size_t)p * EE + pos] = src[(size_t)p * EE + e];
}

// ---------------- K5: fused GAT per dst node (warp per node) + BN stats ----------------
__device__ __forceinline__ float lrelu(float v) { return v > 0.f ? v : SLOPE * v; }
#define ONLINE_UPD(v, m, d) \
    do { if ((v) > (m)) { (d) = (d) * __expf((m) - (v)) + 1.f; (m) = (v); } \
         else (d) += __expf((v) - (m)); } while (0)

__global__ void __launch_bounds__(256) k_gat(
    int p, const float* __restrict__ h, float* __restrict__ attn_out) {
    __shared__ float s_sum[CIN], s_sq[CIN];
    int tid = threadIdx.x;
    s_sum[tid] = 0.f; s_sq[tid] = 0.f;
    __syncthreads();

    int gw = (blockIdx.x * blockDim.x + tid) >> 5;    // node id (grid sized exactly)
    int lane = tid & 31;
    int n = gw;
    int beg = g_rowptr[p * (NN + 1) + n];
    int end = g_rowptr[p * (NN + 1) + n + 1];

    float4 acc0 = make_float4(0.f, 0.f, 0.f, 0.f);
    float4 acc1 = make_float4(0.f, 0.f, 0.f, 0.f);

    if (end > beg) {
        float4 er4 = *(const float4*)(g_er + ((size_t)p * NN + n) * HH);

        // pass A: online softmax (max + denom in one traversal)
        float m0 = -1e30f, m1 = -1e30f, m2 = -1e30f, m3 = -1e30f;
        float d0 = 0.f, d1 = 0.f, d2 = 0.f, d3 = 0.f;
        for (int j = beg + lane; j < end; j += 32) {
            int s = g_esrc[(size_t)p * EE + j];
            float4 el4 = *(const float4*)(g_el + ((size_t)p * NN + s) * HH);
            float v0 = lrelu(el4.x + er4.x), v1 = lrelu(el4.y + er4.y);
            float v2 = lrelu(el4.z + er4.z), v3 = lrelu(el4.w + er4.w);
            ONLINE_UPD(v0, m0, d0); ONLINE_UPD(v1, m1, d1);
            ONLINE_UPD(v2, m2, d2); ONLINE_UPD(v3, m3, d3);
        }
        // combine: global max then rescaled sums
        float M0 = m0, M1 = m1, M2 = m2, M3 = m3;
        #pragma unroll
        for (int off = 16; off; off >>= 1) {
            M0 = fmaxf(M0, __shfl_xor_sync(0xffffffffu, M0, off));
            M1 = fmaxf(M1, __shfl_xor_sync(0xffffffffu, M1, off));
            M2 = fmaxf(M2, __shfl_xor_sync(0xffffffffu, M2, off));
            M3 = fmaxf(M3, __shfl_xor_sync(0xffffffffu, M3, off));
        }
        d0 *= __expf(m0 - M0); d1 *= __expf(m1 - M1);
        d2 *= __expf(m2 - M2); d3 *= __expf(m3 - M3);
        #pragma unroll
        for (int off = 16; off; off >>= 1) {
            d0 += __shfl_xor_sync(0xffffffffu, d0, off);
            d1 += __shfl_xor_sync(0xffffffffu, d1, off);
            d2 += __shfl_xor_sync(0xffffffffu, d2, off);
            d3 += __shfl_xor_sync(0xffffffffu, d3, off);
        }
        float i0 = d0 > 0.f ? 1.f / d0 : 0.f;
        float i1 = d1 > 0.f ? 1.f / d1 : 0.f;
        float i2 = d2 > 0.f ? 1.f / d2 : 0.f;
        float i3 = d3 > 0.f ? 1.f / d3 : 0.f;

        // pass B: alpha + aggregation
        for (int jb = beg; jb < end; jb += 32) {
            int j = jb + lane;
            int sj = 0;
            float a0 = 0.f, a1 = 0.f, a2 = 0.f, a3 = 0.f;
            if (j < end) {
                int eid = g_eidx[(size_t)p * EE + j];
                sj = g_esrc[(size_t)p * EE + j];
                float4 el4 = *(const float4*)(g_el + ((size_t)p * NN + sj) * HH);
                a0 = __expf(lrelu(el4.x + er4.x) - M0) * i0;
                a1 = __expf(lrelu(el4.y + er4.y) - M1) * i1;
                a2 = __expf(lrelu(el4.z + er4.z) - M2) * i2;
                a3 = __expf(lrelu(el4.w + er4.w) - M3) * i3;
                attn_out[(size_t)p * EE + eid] = 0.25f * (a0 + a1 + a2 + a3);
            }
            int cnt = min(32, end - jb);
            for (int t = 0; t < cnt; t++) {
                int s_t  = __shfl_sync(0xffffffffu, sj, t);
                float b0 = __shfl_sync(0xffffffffu, a0, t);
                float b1 = __shfl_sync(0xffffffffu, a1, t);
                float b2 = __shfl_sync(0xffffffffu, a2, t);
                float b3 = __shfl_sync(0xffffffffu, a3, t);
                const float4* fp = (const float4*)(g_feat + ((size_t)p * NN + s_t) * CIN);
                float4 f0 = fp[lane];
                float4 f1 = fp[lane + 32];
                float w0 = (lane < 16) ? b0 : b1;
                float w1 = (lane < 16) ? b2 : b3;
                acc0.x += f0.x * w0; acc0.y += f0.y * w0;
                acc0.z += f0.z * w0; acc0.w += f0.w * w0;
                acc1.x += f1.x * w1; acc1.y += f1.y * w1;
                acc1.z += f1.z * w1; acc1.w += f1.w * w1;
            }
        }
    }

    // epilogue: x = relu(out) + h, store, block-level BN stats
    const float4* hp = (const float4*)(h + (size_t)n * CIN);
    float4 h0 = hp[lane], h1 = hp[lane + 32];
    float4 x0, x1;
    x0.x = fmaxf(acc0.x, 0.f) + h0.x; x0.y = fmaxf(acc0.y, 0.f) + h0.y;
    x0.z = fmaxf(acc0.z, 0.f) + h0.z; x0.w = fmaxf(acc0.w, 0.f) + h0.w;
    x1.x = fmaxf(acc1.x, 0.f) + h1.x; x1.y = fmaxf(acc1.y, 0.f) + h1.y;
    x1.z = fmaxf(acc1.z, 0.f) + h1.z; x1.w = fmaxf(acc1.w, 0.f) + h1.w;
    float4* op = (float4*)(g_accum + ((size_t)p * NN + n) * CIN);
    op[lane] = x0; op[lane + 32] = x1;

    int c0 = lane * 4, c1 = (lane + 32) * 4;
    atomicAdd(&s_sum[c0+0], x0.x); atomicAdd(&s_sq[c0+0], x0.x*x0.x);
    atomicAdd(&s_sum[c0+1], x0.y); atomicAdd(&s_sq[c0+1], x0.y*x0.y);
    atomicAdd(&s_sum[c0+2], x0.z); atomicAdd(&s_sq[c0+2], x0.z*x0.z);
    atomicAdd(&s_sum[c0+3], x0.w); atomicAdd(&s_sq[c0+3], x0.w*x0.w);
    atomicAdd(&s_sum[c1+0], x1.x); atomicAdd(&s_sq[c1+0], x1.x*x1.x);
    atomicAdd(&s_sum[c1+1], x1.y); atomicAdd(&s_sq[c1+1], x1.y*x1.y);
    atomicAdd(&s_sum[c1+2], x1.z); atomicAdd(&s_sq[c1+2], x1.z*x1.z);
    atomicAdd(&s_sum[c1+3], x1.w); atomicAdd(&s_sq[c1+3], x1.w*x1.w);
    __syncthreads();
    atomicAdd(&g_sum[p * CIN + tid], s_sum[tid]);
    atomicAdd(&g_sumsq[p * CIN + tid], s_sq[tid]);
}

// ---------------- K7: BN affine ----------------
__global__ void k_bnfin(const float* __restrict__ gamma, const float* __restrict__ beta) {
    int p = blockIdx.z; int c = threadIdx.x;
    float mu  = g_sum[p * CIN + c] * (1.f / NN);
    float var = g_sumsq[p * CIN + c] * (1.f / NN) - mu * mu;
    float sc = gamma[c] * rsqrtf(var + EPS);
    g_scale[p * CIN + c] = sc;
    g_shift[p * CIN + c] = beta[c] - sc * mu;
}

// ---------------- K8: pooled output ----------------
__global__ void k_pool(const float* __restrict__ wmat, float* __restrict__ pooled) {
    int idx = blockIdx.x * blockDim.x + threadIdx.x;
    if (idx >= NN * 64) return;
    int n = idx >> 6, c4 = (idx & 63) * 4;
    float4 acc = make_float4(0.f, 0.f, 0.f, 0.f);
    #pragma unroll
    for (int p = 0; p < PP; p++) {
        float wv = wmat[n * PP + p];
        float4 x  = *(const float4*)(g_accum + ((size_t)p * NN + n) * CIN + c4);
        float4 sc = *(const float4*)(g_scale + p * CIN + c4);
        float4 sh = *(const float4*)(g_shift + p * CIN + c4);
        acc.x += wv * (sc.x * x.x + sh.x);
        acc.y += wv * (sc.y * x.y + sh.y);
        acc.z += wv * (sc.z * x.z + sh.z);
        acc.w += wv * (sc.w * x.w + sh.w);
    }
    *(float4*)(pooled + (size_t)n * CIN + c4) = acc;
}

// ---------------- host ----------------
extern "C" void kernel_launch(void* const* d_in, const int* in_sizes, int n_in,
                              void* d_out, int out_size) {
    const float* h     = (const float*)d_in[0];
    const float* mask  = (const float*)d_in[1];
    const int*   src   = (const int*)  d_in[2];
    const int*   dst   = (const int*)  d_in[3];
    const float* fc    = (const float*)d_in[4];
    const float* al    = (const float*)d_in[5];
    const float* ar    = (const float*)d_in[6];
    const float* gamma = (const float*)d_in[7];
    const float* beta  = (const float*)d_in[8];

    float* out    = (float*)d_out;
    float* pooled = out;
    float* wout   = out + (size_t)NN * CIN;
    float* attn   = wout + (size_t)NN * PP;

    cudaFuncSetAttribute(k_mma, cudaFuncAttributeMaxDynamicSharedMemorySize, SMTOT);

    k_zero<<<(PP * NN + 255) / 256, 256>>>();
    k_w<<<(NN + 255) / 256, 256>>>(mask, wout);

    k_cvt_h<<<(int)(((size_t)NN * CIN + 255) / 256), 256>>>(h);
    k_cvt_w<<<(PP * CIN * CIN + 255) / 256, 256>>>(fc);

    dim3 gm(CIN / 128, (NN + 127) / 128, PP);
    k_mma<<<gm, 256, SMTOT>>>(al, ar);

    k_hist<<<dim3((EE + 255) / 256, 1, PP), 256>>>(dst);
    k_scanA<<<dim3(49, 1, PP), 1024>>>();
    k_scanB<<<dim3(1, 1, PP), 64>>>();
    k_scanC<<<dim3(49, 1, PP), 1024>>>();
    k_fill<<<dim3((EE + 255) / 256, 1, PP), 256>>>(dst, src);

    for (int p = 0; p < PP; p++)
        k_gat<<<(NN * 32) / 256, 256>>>(p, h, attn);

    k_bnfin<<<dim3(1, 1, PP), 256>>>(gamma, beta);
    k_pool<<<(NN * 64 + 255) / 256, 256>>>(wout, pooled);
}